// round 15
// baseline (speedup 1.0000x reference)
#include <cuda_runtime.h>
#include <stdint.h>

#define B 8
#define H 1024
#define W 1024
#define NPIX (H * W)
#define SAL_ELEMS (B * 3 * NPIX)
#define NPAIRS (H * (W - 1))
#define NAB 52        // merged band count
#define SLOTS 4       // max atomic bands overlapped by a 16-row chunk (<=3, +1 margin)

// ---------------- scratch ----------------
__device__ float g_partial[B * 64 * SLOTS * W];   // per-chunk band partials, 8 MB
__device__ unsigned g_d2part[B * 64];
__device__ int g_tier[B];
__device__ float g_segmean[B * 3 * 256];

// tier x map geometry: n = BASE[t]+(m-1)*INCR[t]; gr=round(sqrt n); gc=ceil(n/gr)
__constant__ int c_gr[3][3] = { {4, 5, 6}, {8, 9, 10}, {11, 12, 13} };
__constant__ int c_gc[3][3] = { {5, 6, 7}, {9, 9, 10}, {12, 13, 14} };
__constant__ int c_base[3] = { 30, 80, 150 };
__constant__ int c_incr[3] = { 10, 15, 25 };

// Merged row-band boundaries: union over gr in {4,5,6,8,9,10,11,12,13} of
// { ceil(1024*k/gr) : k=0..gr-1 }, sorted, + sentinel 1024. 52 bands.
__constant__ int c_bs[NAB + 1] = {
    0, 79, 86, 94, 103, 114, 128, 158, 171, 187, 205, 228, 237, 256, 280,
    308, 316, 342, 373, 384, 394, 410, 427, 456, 466, 473, 512, 552, 559,
    569, 598, 615, 631, 640, 652, 683, 709, 717, 745, 768, 788, 797, 820,
    838, 854, 867, 896, 911, 922, 931, 939, 946, 1024
};

// ---------------- K1: fused gray + complexity + chunk-private band partials ----
// Block = (b, 16-row chunk): 512 balanced blocks. Per-thread accumulator flushes
// at band boundaries with ONE plain float4 store to this chunk's own slot.
// No atomics, no zero-init pass.
__global__ __launch_bounds__(256) void k_gray(const float* __restrict__ img) {
    __shared__ unsigned s_w[8];

    int chunk = blockIdx.x & 63;
    int b = blockIdx.x >> 6;
    int rc0 = chunk << 4;
    int t = threadIdx.x;
    int col = t << 2;
    int lane = t & 31;
    unsigned mask = 0xFFFFFFFFu;

    // band containing rc0 (uniform walk over constant table)
    int ab = 0;
    while (c_bs[ab + 1] <= rc0) ab++;
    int next = c_bs[ab + 1];
    int slot = 0;

    float4 acc = make_float4(0.f, 0.f, 0.f, 0.f);
    bool dirty = false;
    unsigned d2 = 0;
    float* pbase = g_partial + (size_t)(b * 64 + chunk) * SLOTS * W + col;
    const float* base = img + (size_t)b * 3 * NPIX + col;

#pragma unroll 4
    for (int rr = 0; rr < 16; rr++) {
        int r = rc0 + rr;
        const float* p = base + (size_t)r * W;
        float4 r4 = __ldcs((const float4*)p);
        float4 g4 = __ldcs((const float4*)(p + NPIX));
        float4 b4 = __ldcs((const float4*)(p + 2 * NPIX));

        float gy0 = 0.299f * r4.x + 0.587f * g4.x + 0.114f * b4.x;
        float gy1 = 0.299f * r4.y + 0.587f * g4.y + 0.114f * b4.y;
        float gy2 = 0.299f * r4.z + 0.587f * g4.z + 0.114f * b4.z;
        float gy3 = 0.299f * r4.w + 0.587f * g4.w + 0.114f * b4.w;

        acc.x += (r4.x + g4.x + b4.x) * (1.0f / 3.0f);
        acc.y += (r4.y + g4.y + b4.y) * (1.0f / 3.0f);
        acc.z += (r4.z + g4.z + b4.z) * (1.0f / 3.0f);
        acc.w += (r4.w + g4.w + b4.w) * (1.0f / 3.0f);
        dirty = true;

        float gnext = __shfl_down_sync(mask, gy0, 1);
        if (lane == 31 && col + 4 < W) {
            const float* q = p + 4;
            gnext = 0.299f * q[0] + 0.587f * q[NPIX] + 0.114f * q[2 * NPIX];
        }

        int i0 = min(max((int)(gy0 * 255.0f), 0), 255);
        int i1 = min(max((int)(gy1 * 255.0f), 0), 255);
        int i2 = min(max((int)(gy2 * 255.0f), 0), 255);
        int i3 = min(max((int)(gy3 * 255.0f), 0), 255);

        int d;
        d = i0 - i1; d2 += (unsigned)(d * d);
        d = i1 - i2; d2 += (unsigned)(d * d);
        d = i2 - i3; d2 += (unsigned)(d * d);
        if (col + 3 < W - 1) {
            int i4 = min(max((int)(gnext * 255.0f), 0), 255);
            d = i3 - i4; d2 += (unsigned)(d * d);
        }

        if (r + 1 == next) {
            *(float4*)(pbase + (size_t)slot * W) = acc;
            acc = make_float4(0.f, 0.f, 0.f, 0.f);
            dirty = false;
            slot++;
            ab++;
            next = c_bs[ab + 1];
        }
    }
    if (dirty) *(float4*)(pbase + (size_t)slot * W) = acc;

    d2 = __reduce_add_sync(mask, d2);
    if (lane == 0) s_w[t >> 5] = d2;
    __syncthreads();
    if (t == 0) {
        unsigned tot = 0;
#pragma unroll
        for (int i = 0; i < 8; i++) tot += s_w[i];
        g_d2part[blockIdx.x] = tot;
    }
}

// ---------------- K2: segment means from chunk partials (tier inline) --------
__global__ __launch_bounds__(32) void k_segmean(float* __restrict__ out, int write_tail) {
    int b = blockIdx.z, m = blockIdx.y, seg = blockIdx.x;
    int lane = threadIdx.x;
    unsigned mask = 0xFFFFFFFFu;

    // inline complexity reduce (64 u32 partials, L2-hot) -> tier, all lanes
    unsigned long long s64 = (unsigned long long)g_d2part[b * 64 + lane]
                           + (unsigned long long)g_d2part[b * 64 + 32 + lane];
#pragma unroll
    for (int o = 16; o > 0; o >>= 1) s64 += __shfl_xor_sync(mask, s64, o);
    float comp = (float)s64 / (float)NPAIRS;
    int tier = (comp < 50.0f) ? 0 : ((comp < 150.0f) ? 1 : 2);

    if (m == 0 && seg == 0 && lane == 0) {
        g_tier[b] = tier;
        if (write_tail) {
            out[SAL_ELEMS + b] = comp;
#pragma unroll
            for (int mm = 0; mm < 3; mm++)
                out[SAL_ELEMS + B + b * 3 + mm] = (float)(c_base[tier] + (mm - 1) * c_incr[tier]);
        }
    }

    int gr = c_gr[tier][m], gc = c_gc[tier][m];
    if (seg >= gr * gc) return;
    int r = seg / gc, c = seg - r * gc;
    int r0 = (r * H + gr - 1) / gr;
    int r1 = ((r + 1) * H + gr - 1) / gr; if (r1 > H) r1 = H;
    int c0 = (c * W + gc - 1) / gc;
    int c1 = ((c + 1) * W + gc - 1) / gc; if (c1 > W) c1 = W;

    float s = 0.0f;
    // sum variant bands tiling [r0,r1); each band sums its overlapping chunks
    for (int ab = 0; ab < NAB; ab++) {
        int bs = c_bs[ab];
        if (bs < r0 || bs >= r1) continue;
        int be = c_bs[ab + 1];
        int cA = bs >> 4, cB = (be - 1) >> 4;
        for (int ch = cA; ch <= cB; ch++) {
            // band index at this chunk's start row (uniform walk)
            int ab0 = 0;
            while (c_bs[ab0 + 1] <= (ch << 4)) ab0++;
            int slot = ab - ab0;
            const float* p = g_partial + ((size_t)(b * 64 + ch) * SLOTS + slot) * W;
            for (int col = c0 + lane; col < c1; col += 32) s += p[col];
        }
    }
#pragma unroll
    for (int o = 16; o > 0; o >>= 1) s += __shfl_down_sync(mask, s, o);
    if (lane == 0) {
        int cnt = (r1 - r0) * (c1 - c0);
        g_segmean[((size_t)b * 3 + m) * 256 + seg] = s / (float)cnt;
    }
}

// ---------------- K3: fill saliency, block-per-row + smem LUT ----------------
// bm/tier/rb uniform per block; per thread: 4 LDS + 1 STG.128. No div, no LDG.
__global__ __launch_bounds__(256) void k_fill(float* __restrict__ out) {
    __shared__ float lut[16];
    int row = blockIdx.x, m = blockIdx.y, b = blockIdx.z;
    int bm = b * 3 + m;
    int tier = g_tier[b];
    int gr = c_gr[tier][m], gc = c_gc[tier][m];
    int rb = (row * gr) >> 10;

    int t = threadIdx.x;
    if (t < 16)
        lut[t] = (t < gc) ? g_segmean[(size_t)bm * 256 + rb * gc + t] : 0.0f;
    __syncthreads();

    int col = t << 2;
    float4 v;
    v.x = lut[((col + 0) * gc) >> 10];
    v.y = lut[((col + 1) * gc) >> 10];
    v.z = lut[((col + 2) * gc) >> 10];
    v.w = lut[((col + 3) * gc) >> 10];
    __stcs((float4*)(out + (size_t)bm * NPIX + (size_t)row * W + col), v);
}

// ---------------- launch ----------------
extern "C" void kernel_launch(void* const* d_in, const int* in_sizes, int n_in,
                              void* d_out, int out_size) {
    const float* img = (const float*)d_in[0];
    float* out = (float*)d_out;
    int write_tail = (out_size >= SAL_ELEMS + B + B * 3) ? 1 : 0;

    k_gray<<<B * 64, 256>>>(img);
    dim3 gsm(182, 3, B);
    k_segmean<<<gsm, 32>>>(out, write_tail);
    dim3 gf(H, 3, B);
    k_fill<<<gf, 256>>>(out);
}

// round 16
// speedup vs baseline: 1.3749x; 1.3749x over previous
#include <cuda_runtime.h>
#include <stdint.h>

#define B 8
#define H 1024
#define W 1024
#define NPIX (H * W)
#define SAL_ELEMS (B * 3 * NPIX)
#define NPAIRS (H * (W - 1))
#define MAXAB 64      // g_aband stride (>= NAB)
#define NAB 52        // merged band count

// ---------------- scratch ----------------
__device__ float g_aband[B * MAXAB * W];      // [b][atomic band][col], 2 MB
__device__ unsigned g_d2part[B * 128];
__device__ int g_tier[B];
__device__ float g_segmean[B * 3 * 256];

// tier x map geometry: n = BASE[t]+(m-1)*INCR[t]; gr=round(sqrt n); gc=ceil(n/gr)
__constant__ int c_gr[3][3] = { {4, 5, 6}, {8, 9, 10}, {11, 12, 13} };
__constant__ int c_gc[3][3] = { {5, 6, 7}, {9, 9, 10}, {12, 13, 14} };
__constant__ int c_base[3] = { 30, 80, 150 };
__constant__ int c_incr[3] = { 10, 15, 25 };

// Merged row-band boundaries: union over gr in {4,5,6,8,9,10,11,12,13} of
// { ceil(1024*k/gr) : k=0..gr-1 }, sorted, + sentinel 1024. 52 bands.
__constant__ int c_bs[NAB + 1] = {
    0, 79, 86, 94, 103, 114, 128, 158, 171, 187, 205, 228, 237, 256, 280,
    308, 316, 342, 373, 384, 394, 410, 427, 456, 466, 473, 512, 552, 559,
    569, 598, 615, 631, 640, 652, 683, 709, 717, 745, 768, 788, 797, 820,
    838, 854, 867, 896, 911, 922, 931, 939, 946, 1024
};

// ---------------- K0: zero atomic-band accumulators ----------------
__global__ __launch_bounds__(256) void k_zero() {
    int i = blockIdx.x * 256 + threadIdx.x;     // float4 index; 512*256 exact
    ((float4*)g_aband)[i] = make_float4(0.f, 0.f, 0.f, 0.f);
}

// ---------------- K1: fused gray + complexity + row-band sums ----------------
// Block = (b, 8-row chunk): 1024 blocks -> ~86% occupancy (512 blocks was
// grid-starved at 42%). Per-thread accumulator flushes to g_aband via
// atomicAdd only at merged band boundaries (<=2 flushes per thread).
__global__ __launch_bounds__(256) void k_gray(const float* __restrict__ img) {
    __shared__ unsigned s_w[8];

    int chunk = blockIdx.x & 127;
    int b = blockIdx.x >> 7;
    int rc0 = chunk << 3;
    int t = threadIdx.x;
    int col = t << 2;
    int lane = t & 31;
    unsigned mask = 0xFFFFFFFFu;

    // locate atomic band containing rc0 (uniform walk over constant table)
    int ab = 0;
    while (c_bs[ab + 1] <= rc0) ab++;
    int next = c_bs[ab + 1];

    float4 acc = make_float4(0.f, 0.f, 0.f, 0.f);
    bool dirty = false;
    unsigned d2 = 0;
    float* abandb = g_aband + (size_t)b * MAXAB * W + col;
    const float* base = img + (size_t)b * 3 * NPIX + col;

#pragma unroll 4
    for (int rr = 0; rr < 8; rr++) {
        int r = rc0 + rr;
        const float* p = base + (size_t)r * W;
        float4 r4 = __ldcs((const float4*)p);
        float4 g4 = __ldcs((const float4*)(p + NPIX));
        float4 b4 = __ldcs((const float4*)(p + 2 * NPIX));

        float gy0 = 0.299f * r4.x + 0.587f * g4.x + 0.114f * b4.x;
        float gy1 = 0.299f * r4.y + 0.587f * g4.y + 0.114f * b4.y;
        float gy2 = 0.299f * r4.z + 0.587f * g4.z + 0.114f * b4.z;
        float gy3 = 0.299f * r4.w + 0.587f * g4.w + 0.114f * b4.w;

        acc.x += (r4.x + g4.x + b4.x) * (1.0f / 3.0f);
        acc.y += (r4.y + g4.y + b4.y) * (1.0f / 3.0f);
        acc.z += (r4.z + g4.z + b4.z) * (1.0f / 3.0f);
        acc.w += (r4.w + g4.w + b4.w) * (1.0f / 3.0f);
        dirty = true;

        float gnext = __shfl_down_sync(mask, gy0, 1);
        if (lane == 31 && col + 4 < W) {
            const float* q = p + 4;
            gnext = 0.299f * q[0] + 0.587f * q[NPIX] + 0.114f * q[2 * NPIX];
        }

        int i0 = min(max((int)(gy0 * 255.0f), 0), 255);
        int i1 = min(max((int)(gy1 * 255.0f), 0), 255);
        int i2 = min(max((int)(gy2 * 255.0f), 0), 255);
        int i3 = min(max((int)(gy3 * 255.0f), 0), 255);

        int d;
        d = i0 - i1; d2 += (unsigned)(d * d);
        d = i1 - i2; d2 += (unsigned)(d * d);
        d = i2 - i3; d2 += (unsigned)(d * d);
        if (col + 3 < W - 1) {
            int i4 = min(max((int)(gnext * 255.0f), 0), 255);
            d = i3 - i4; d2 += (unsigned)(d * d);
        }

        if (r + 1 == next) {
            float* dst = abandb + (size_t)ab * W;
            atomicAdd(dst + 0, acc.x);
            atomicAdd(dst + 1, acc.y);
            atomicAdd(dst + 2, acc.z);
            atomicAdd(dst + 3, acc.w);
            acc = make_float4(0.f, 0.f, 0.f, 0.f);
            dirty = false;
            ab++;
            next = c_bs[ab + 1];
        }
    }
    if (dirty) {
        float* dst = abandb + (size_t)ab * W;
        atomicAdd(dst + 0, acc.x);
        atomicAdd(dst + 1, acc.y);
        atomicAdd(dst + 2, acc.z);
        atomicAdd(dst + 3, acc.w);
    }

    d2 = __reduce_add_sync(mask, d2);
    if (lane == 0) s_w[t >> 5] = d2;
    __syncthreads();
    if (t == 0) {
        unsigned tot = 0;
#pragma unroll
        for (int i = 0; i < 8; i++) tot += s_w[i];
        g_d2part[blockIdx.x] = tot;
    }
}

// ---------------- K2: segment means (tier computed inline) ----------------
__global__ __launch_bounds__(32) void k_segmean(float* __restrict__ out, int write_tail) {
    int b = blockIdx.z, m = blockIdx.y, seg = blockIdx.x;
    int lane = threadIdx.x;
    unsigned mask = 0xFFFFFFFFu;

    // inline complexity reduce (128 u32 partials, L2-hot) -> tier, all lanes
    unsigned long long s64 = (unsigned long long)g_d2part[b * 128 + lane]
                           + (unsigned long long)g_d2part[b * 128 + 32 + lane]
                           + (unsigned long long)g_d2part[b * 128 + 64 + lane]
                           + (unsigned long long)g_d2part[b * 128 + 96 + lane];
#pragma unroll
    for (int o = 16; o > 0; o >>= 1) s64 += __shfl_xor_sync(mask, s64, o);
    float comp = (float)s64 / (float)NPAIRS;
    int tier = (comp < 50.0f) ? 0 : ((comp < 150.0f) ? 1 : 2);

    if (m == 0 && seg == 0 && lane == 0) {
        g_tier[b] = tier;
        if (write_tail) {
            out[SAL_ELEMS + b] = comp;
#pragma unroll
            for (int mm = 0; mm < 3; mm++)
                out[SAL_ELEMS + B + b * 3 + mm] = (float)(c_base[tier] + (mm - 1) * c_incr[tier]);
        }
    }

    int gr = c_gr[tier][m], gc = c_gc[tier][m];
    if (seg >= gr * gc) return;
    int r = seg / gc, c = seg - r * gc;
    int r0 = (r * H + gr - 1) / gr;
    int r1 = ((r + 1) * H + gr - 1) / gr; if (r1 > H) r1 = H;
    int c0 = (c * W + gc - 1) / gc;
    int c1 = ((c + 1) * W + gc - 1) / gc; if (c1 > W) c1 = W;

    float s = 0.0f;
    for (int ab = 0; ab < NAB; ab++) {
        int bs = c_bs[ab];
        if (bs >= r0 && bs < r1) {
            const float* p = g_aband + ((size_t)b * MAXAB + ab) * W;
            for (int col = c0 + lane; col < c1; col += 32) s += p[col];
        }
    }
#pragma unroll
    for (int o = 16; o > 0; o >>= 1) s += __shfl_down_sync(mask, s, o);
    if (lane == 0) {
        int cnt = (r1 - r0) * (c1 - c0);
        g_segmean[((size_t)b * 3 + m) * 256 + seg] = s / (float)cnt;
    }
}

// ---------------- K3: fill saliency, 4 floats/thread (proven-best form) ----------
__global__ __launch_bounds__(256) void k_fill(float* __restrict__ out) {
    int idx = blockIdx.x * blockDim.x + threadIdx.x;   // quad index
    int bm = idx >> 18;
    int within = idx & 262143;
    int row = within >> 8;
    int col = (within & 255) << 2;

    int b = bm / 3;
    int m = bm - b * 3;
    int tier = g_tier[b];
    int gr = c_gr[tier][m], gc = c_gc[tier][m];
    const float* sm = g_segmean + (size_t)bm * 256;

    int rb = (row * gr) >> 10;
    int basei = rb * gc;
    float4 v;
    v.x = sm[basei + (((col + 0) * gc) >> 10)];
    v.y = sm[basei + (((col + 1) * gc) >> 10)];
    v.z = sm[basei + (((col + 2) * gc) >> 10)];
    v.w = sm[basei + (((col + 3) * gc) >> 10)];
    __stcs((float4*)(out + (size_t)bm * NPIX + (size_t)row * W + col), v);
}

// ---------------- launch ----------------
extern "C" void kernel_launch(void* const* d_in, const int* in_sizes, int n_in,
                              void* d_out, int out_size) {
    const float* img = (const float*)d_in[0];
    float* out = (float*)d_out;
    int write_tail = (out_size >= SAL_ELEMS + B + B * 3) ? 1 : 0;

    k_zero<<<512, 256>>>();
    k_gray<<<B * 128, 256>>>(img);
    dim3 gsm(182, 3, B);
    k_segmean<<<gsm, 32>>>(out, write_tail);
    k_fill<<<(SAL_ELEMS / 4) / 256, 256>>>(out);
}

// round 17
// speedup vs baseline: 1.3848x; 1.0072x over previous
#include <cuda_runtime.h>
#include <stdint.h>

#define B 8
#define H 1024
#define W 1024
#define NPIX (H * W)
#define SAL_ELEMS (B * 3 * NPIX)
#define NPAIRS (H * (W - 1))
#define MAXAB 64      // g_aband stride (>= NAB)
#define NAB 52        // merged band count

// ---------------- scratch ----------------
__device__ float g_aband[B * MAXAB * W];      // [b][atomic band][col], 2 MB
__device__ unsigned g_d2part[B * 128];
__device__ int g_tier[B];
__device__ float g_segmean[B * 3 * 256];

// tier x map geometry: n = BASE[t]+(m-1)*INCR[t]; gr=round(sqrt n); gc=ceil(n/gr)
__constant__ int c_gr[3][3] = { {4, 5, 6}, {8, 9, 10}, {11, 12, 13} };
__constant__ int c_gc[3][3] = { {5, 6, 7}, {9, 9, 10}, {12, 13, 14} };
__constant__ int c_base[3] = { 30, 80, 150 };
__constant__ int c_incr[3] = { 10, 15, 25 };

// Merged row-band boundaries: union over gr in {4,5,6,8,9,10,11,12,13} of
// { ceil(1024*k/gr) : k=0..gr-1 }, sorted, + sentinel 1024. 52 bands.
__constant__ int c_bs[NAB + 1] = {
    0, 79, 86, 94, 103, 114, 128, 158, 171, 187, 205, 228, 237, 256, 280,
    308, 316, 342, 373, 384, 394, 410, 427, 456, 466, 473, 512, 552, 559,
    569, 598, 615, 631, 640, 652, 683, 709, 717, 745, 768, 788, 797, 820,
    838, 854, 867, 896, 911, 922, 931, 939, 946, 1024
};

// ---------------- K0: zero atomic-band accumulators ----------------
__global__ __launch_bounds__(256) void k_zero() {
    int i = blockIdx.x * 256 + threadIdx.x;     // float4 index; 512*256 exact
    ((float4*)g_aband)[i] = make_float4(0.f, 0.f, 0.f, 0.f);
}

// ---------------- K1: fused gray + complexity + row-band sums ----------------
// Block = (b, 8-row chunk): 1024 blocks -> ~86% occupancy. Per-thread
// accumulator flushes to g_aband via atomicAdd only at merged band boundaries.
__global__ __launch_bounds__(256) void k_gray(const float* __restrict__ img) {
    __shared__ unsigned s_w[8];

    int chunk = blockIdx.x & 127;
    int b = blockIdx.x >> 7;
    int rc0 = chunk << 3;
    int t = threadIdx.x;
    int col = t << 2;
    int lane = t & 31;
    unsigned mask = 0xFFFFFFFFu;

    // locate atomic band containing rc0 (uniform walk over constant table)
    int ab = 0;
    while (c_bs[ab + 1] <= rc0) ab++;
    int next = c_bs[ab + 1];

    float4 acc = make_float4(0.f, 0.f, 0.f, 0.f);
    bool dirty = false;
    unsigned d2 = 0;
    float* abandb = g_aband + (size_t)b * MAXAB * W + col;
    const float* base = img + (size_t)b * 3 * NPIX + col;

#pragma unroll 4
    for (int rr = 0; rr < 8; rr++) {
        int r = rc0 + rr;
        const float* p = base + (size_t)r * W;
        float4 r4 = __ldcs((const float4*)p);
        float4 g4 = __ldcs((const float4*)(p + NPIX));
        float4 b4 = __ldcs((const float4*)(p + 2 * NPIX));

        float gy0 = 0.299f * r4.x + 0.587f * g4.x + 0.114f * b4.x;
        float gy1 = 0.299f * r4.y + 0.587f * g4.y + 0.114f * b4.y;
        float gy2 = 0.299f * r4.z + 0.587f * g4.z + 0.114f * b4.z;
        float gy3 = 0.299f * r4.w + 0.587f * g4.w + 0.114f * b4.w;

        acc.x += (r4.x + g4.x + b4.x) * (1.0f / 3.0f);
        acc.y += (r4.y + g4.y + b4.y) * (1.0f / 3.0f);
        acc.z += (r4.z + g4.z + b4.z) * (1.0f / 3.0f);
        acc.w += (r4.w + g4.w + b4.w) * (1.0f / 3.0f);
        dirty = true;

        float gnext = __shfl_down_sync(mask, gy0, 1);
        if (lane == 31 && col + 4 < W) {
            const float* q = p + 4;
            gnext = 0.299f * q[0] + 0.587f * q[NPIX] + 0.114f * q[2 * NPIX];
        }

        int i0 = min(max((int)(gy0 * 255.0f), 0), 255);
        int i1 = min(max((int)(gy1 * 255.0f), 0), 255);
        int i2 = min(max((int)(gy2 * 255.0f), 0), 255);
        int i3 = min(max((int)(gy3 * 255.0f), 0), 255);

        int d;
        d = i0 - i1; d2 += (unsigned)(d * d);
        d = i1 - i2; d2 += (unsigned)(d * d);
        d = i2 - i3; d2 += (unsigned)(d * d);
        if (col + 3 < W - 1) {
            int i4 = min(max((int)(gnext * 255.0f), 0), 255);
            d = i3 - i4; d2 += (unsigned)(d * d);
        }

        if (r + 1 == next) {
            float* dst = abandb + (size_t)ab * W;
            atomicAdd(dst + 0, acc.x);
            atomicAdd(dst + 1, acc.y);
            atomicAdd(dst + 2, acc.z);
            atomicAdd(dst + 3, acc.w);
            acc = make_float4(0.f, 0.f, 0.f, 0.f);
            dirty = false;
            ab++;
            next = c_bs[ab + 1];
        }
    }
    if (dirty) {
        float* dst = abandb + (size_t)ab * W;
        atomicAdd(dst + 0, acc.x);
        atomicAdd(dst + 1, acc.y);
        atomicAdd(dst + 2, acc.z);
        atomicAdd(dst + 3, acc.w);
    }

    d2 = __reduce_add_sync(mask, d2);
    if (lane == 0) s_w[t >> 5] = d2;
    __syncthreads();
    if (t == 0) {
        unsigned tot = 0;
#pragma unroll
        for (int i = 0; i < 8; i++) tot += s_w[i];
        g_d2part[blockIdx.x] = tot;
    }
}

// ---------------- K2: segment means (tier computed inline) ----------------
__global__ __launch_bounds__(32) void k_segmean(float* __restrict__ out, int write_tail) {
    int b = blockIdx.z, m = blockIdx.y, seg = blockIdx.x;
    int lane = threadIdx.x;
    unsigned mask = 0xFFFFFFFFu;

    // inline complexity reduce (128 u32 partials, L2-hot) -> tier, all lanes
    unsigned long long s64 = (unsigned long long)g_d2part[b * 128 + lane]
                           + (unsigned long long)g_d2part[b * 128 + 32 + lane]
                           + (unsigned long long)g_d2part[b * 128 + 64 + lane]
                           + (unsigned long long)g_d2part[b * 128 + 96 + lane];
#pragma unroll
    for (int o = 16; o > 0; o >>= 1) s64 += __shfl_xor_sync(mask, s64, o);
    float comp = (float)s64 / (float)NPAIRS;
    int tier = (comp < 50.0f) ? 0 : ((comp < 150.0f) ? 1 : 2);

    if (m == 0 && seg == 0 && lane == 0) {
        g_tier[b] = tier;
        if (write_tail) {
            out[SAL_ELEMS + b] = comp;
#pragma unroll
            for (int mm = 0; mm < 3; mm++)
                out[SAL_ELEMS + B + b * 3 + mm] = (float)(c_base[tier] + (mm - 1) * c_incr[tier]);
        }
    }

    int gr = c_gr[tier][m], gc = c_gc[tier][m];
    if (seg >= gr * gc) return;
    int r = seg / gc, c = seg - r * gc;
    int r0 = (r * H + gr - 1) / gr;
    int r1 = ((r + 1) * H + gr - 1) / gr; if (r1 > H) r1 = H;
    int c0 = (c * W + gc - 1) / gc;
    int c1 = ((c + 1) * W + gc - 1) / gc; if (c1 > W) c1 = W;

    float s = 0.0f;
    for (int ab = 0; ab < NAB; ab++) {
        int bs = c_bs[ab];
        if (bs >= r0 && bs < r1) {
            const float* p = g_aband + ((size_t)b * MAXAB + ab) * W;
            for (int col = c0 + lane; col < c1; col += 32) s += p[col];
        }
    }
#pragma unroll
    for (int o = 16; o > 0; o >>= 1) s += __shfl_down_sync(mask, s, o);
    if (lane == 0) {
        int cnt = (r1 - r0) * (c1 - c0);
        g_segmean[((size_t)b * 3 + m) * 256 + seg] = s / (float)cnt;
    }
}

// ---------------- K3: fill saliency — block-uniform indices, 4 floats/thread ----
// grid = (row, bm): bm/b/m/tier/gr/gc/rb all uniform per block; per thread
// only the 4 column-band lookups + one STG.128 remain.
__global__ __launch_bounds__(256) void k_fill(float* __restrict__ out) {
    int row = blockIdx.x;          // 0..1023
    int bm = blockIdx.y;           // 0..23
    int b = bm / 3;                // uniform
    int m = bm - b * 3;
    int tier = g_tier[b];
    int gr = c_gr[tier][m], gc = c_gc[tier][m];
    int rb = (row * gr) >> 10;
    const float* sm = g_segmean + (size_t)bm * 256 + rb * gc;

    int col = threadIdx.x << 2;
    float4 v;
    v.x = sm[((col + 0) * gc) >> 10];
    v.y = sm[((col + 1) * gc) >> 10];
    v.z = sm[((col + 2) * gc) >> 10];
    v.w = sm[((col + 3) * gc) >> 10];
    __stcs((float4*)(out + (size_t)bm * NPIX + (size_t)row * W + col), v);
}

// ---------------- launch ----------------
extern "C" void kernel_launch(void* const* d_in, const int* in_sizes, int n_in,
                              void* d_out, int out_size) {
    const float* img = (const float*)d_in[0];
    float* out = (float*)d_out;
    int write_tail = (out_size >= SAL_ELEMS + B + B * 3) ? 1 : 0;

    k_zero<<<512, 256>>>();
    k_gray<<<B * 128, 256>>>(img);
    dim3 gsm(182, 3, B);
    k_segmean<<<gsm, 32>>>(out, write_tail);
    dim3 gf(H, 3 * B);
    k_fill<<<gf, 256>>>(out);
}